// round 14
// baseline (speedup 1.0000x reference)
#include <cuda_runtime.h>
#include <cuda_fp16.h>
#include <math.h>
#include <stdint.h>

#define NN 50000
#define EE 800000
#define DD 128
#define OUTC 64
#define NBLK ((NN + 1023) / 1024)   // 49 scan blocks

typedef unsigned long long u64;

// ---------------- scratch (device globals; no allocation allowed) ----------
__device__ int   g_ei_is64;
__device__ int   g_m_is32;
__device__ int   g_deg[NN];
__device__ float g_dinv[NN];
__device__ int   g_off[NN + 1];
__device__ int   g_bsum[64];        // raw per-block sums from scanA
__device__ int   g_rank[EE];        // per-edge rank within its column
__device__ int   g_src[EE];
__device__ __half g_xt[NN * DD];    // x_tilde, fp16, pre-scaled by dinv[row]
__device__ __half g_x0[NN * DD];    // hrn(dinv*x) where mask=1, NaN where mask=0
__device__ __half g_agg[NN * DD];   // aggregated messages (fp16)

// ---------------- f32x2 packed math ----------------------------------------
__device__ __forceinline__ u64 pack2(float s) {
    u64 d;
    asm("mov.b64 %0, {%1, %1};" : "=l"(d) : "f"(s));
    return d;
}
__device__ __forceinline__ void fma2(u64& acc, u64 a, u64 b) {
    asm("fma.rn.f32x2 %0, %1, %2, %0;" : "+l"(acc) : "l"(a), "l"(b));
}
__device__ __forceinline__ float2 unpack2(u64 v) {
    float lo, hi;
    asm("mov.b64 {%0, %1}, %2;" : "=f"(lo), "=f"(hi) : "l"(v));
    return make_float2(lo, hi);
}

// ---------------- init: zero deg + dtype detection ---------------------------
__global__ void k_init(const int* __restrict__ ei, const unsigned int* __restrict__ Mw) {
    int i = blockIdx.x * blockDim.x + threadIdx.x;
    if (i < NN) g_deg[i] = 0;
    if (blockIdx.x == 0) {
        __shared__ int s_or, s_gt;
        if (threadIdx.x == 0) { s_or = 0; s_gt = 0; }
        __syncthreads();
        int t = threadIdx.x;
        if (ei[2 * t + 1] != 0) atomicOr(&s_or, 1);
        if (Mw[t] > 1u)         atomicOr(&s_gt, 1);
        __syncthreads();
        if (threadIdx.x == 0) { g_ei_is64 = (s_or == 0); g_m_is32 = (s_gt == 0); }
    }
}

// ---------------- CSC build: count assigns per-edge ranks --------------------
__global__ void k_count(const int* __restrict__ ei) {
    int e = blockIdx.x * blockDim.x + threadIdx.x;
    if (e >= EE) return;
    int c = g_ei_is64 ? ei[2 * (EE + e)] : ei[EE + e];
    g_rank[e] = atomicAdd(&g_deg[c], 1);
}

__global__ void k_scanA() {
    __shared__ int wsum[32];
    int tid = threadIdx.x, lane = tid & 31, wid = tid >> 5;
    int i = blockIdx.x * 1024 + tid;
    int v = (i < NN) ? g_deg[i] : 0;
    if (i < NN) g_dinv[i] = (v > 0) ? rsqrtf((float)v) : 0.0f;
    int x = v;
#pragma unroll
    for (int o = 1; o < 32; o <<= 1) {
        int t = __shfl_up_sync(0xffffffffu, x, o);
        if (lane >= o) x += t;
    }
    if (lane == 31) wsum[wid] = x;
    __syncthreads();
    if (wid == 0) {
        int s = wsum[lane];
#pragma unroll
        for (int o = 1; o < 32; o <<= 1) {
            int t = __shfl_up_sync(0xffffffffu, s, o);
            if (lane >= o) s += t;
        }
        wsum[lane] = s;
    }
    __syncthreads();
    int woff = (wid > 0) ? wsum[wid - 1] : 0;
    if (i < NN) g_off[i + 1] = woff + x;          // block-local inclusive
    if (tid == 1023) g_bsum[blockIdx.x] = woff + x;   // raw block sum
}

// ---------------- fix offsets (local bsum prefix) + x_tilde/x0 init ----------
__global__ void k_fix_xt(const float* __restrict__ x, const void* __restrict__ M) {
    __shared__ int sb[NBLK];
    int tid = threadIdx.x;
    int gid = blockIdx.x * blockDim.x + tid;
    if (tid < NBLK) sb[tid] = g_bsum[tid];
    __syncthreads();
    if (tid == 0) {                 // exclusive prefix of 49 values
        int acc = 0;
#pragma unroll
        for (int q = 0; q < NBLK; q++) { int t = sb[q]; sb[q] = acc; acc += t; }
    }
    __syncthreads();
    if (gid < NN) g_off[gid + 1] += sb[gid >> 10];
    if (gid == 0) g_off[0] = 0;

    int i = gid;                                   // over (N*D)/4
    if (i >= NN * DD / 4) return;
    uchar4 mv;
    if (g_m_is32) {
        int4 w = ((const int4*)M)[i];
        mv = make_uchar4((unsigned char)w.x, (unsigned char)w.y,
                         (unsigned char)w.z, (unsigned char)w.w);
    } else {
        mv = ((const uchar4*)M)[i];
    }
    float dv = g_dinv[i >> 5];
    float4 xv = ((const float4*)x)[i];
    float s0 = dv * xv.x, s1 = dv * xv.y, s2 = dv * xv.z, s3 = dv * xv.w;
    __half2 xt01 = __floats2half2_rn(mv.x ? s0 : 0.0f, mv.y ? s1 : 0.0f);
    __half2 xt23 = __floats2half2_rn(mv.z ? s2 : 0.0f, mv.w ? s3 : 0.0f);
    const float QNAN = __int_as_float(0x7fc00000);
    __half2 x001 = __floats2half2_rn(mv.x ? s0 : QNAN, mv.y ? s1 : QNAN);
    __half2 x023 = __floats2half2_rn(mv.z ? s2 : QNAN, mv.w ? s3 : QNAN);
    uint2 pxt, px0;
    pxt.x = *(unsigned int*)&xt01; pxt.y = *(unsigned int*)&xt23;
    px0.x = *(unsigned int*)&x001; px0.y = *(unsigned int*)&x023;
    ((uint2*)g_xt)[i] = pxt;
    ((uint2*)g_x0)[i] = px0;
}

// ---------------- bucket: pure scattered store (no atomics) ------------------
__global__ void k_bucket(const int* __restrict__ ei) {
    int e = blockIdx.x * blockDim.x + threadIdx.x;
    if (e >= EE) return;
    int r, c;
    if (g_ei_is64) { r = ei[2 * e]; c = ei[2 * (EE + e)]; }
    else           { r = ei[e];     c = ei[EE + e]; }
    g_src[g_off[c] + g_rank[e]] = r;
}

// ---------------- SpMM: one warp per destination node (fp16 in/out) ----------
__global__ void k_spmm() {
    int warp = (blockIdx.x * blockDim.x + threadIdx.x) >> 5;
    if (warp >= NN) return;
    int lane = threadIdx.x & 31;
    int s = g_off[warp], t = g_off[warp + 1];
    const uint2* xt2 = (const uint2*)g_xt;   // 8B = 4 halfs per lane
    float4 acc = make_float4(0.f, 0.f, 0.f, 0.f);
    int i = s;
    for (; i + 8 <= t; i += 8) {
        uint2 rv[8];
#pragma unroll
        for (int u = 0; u < 8; u++) rv[u] = xt2[g_src[i + u] * 32 + lane];
#pragma unroll
        for (int u = 0; u < 8; u++) {
            float2 f01 = __half22float2(*(__half2*)&rv[u].x);
            float2 f23 = __half22float2(*(__half2*)&rv[u].y);
            acc.x += f01.x; acc.y += f01.y; acc.z += f23.x; acc.w += f23.y;
        }
    }
    for (; i + 4 <= t; i += 4) {
        uint2 rv[4];
#pragma unroll
        for (int u = 0; u < 4; u++) rv[u] = xt2[g_src[i + u] * 32 + lane];
#pragma unroll
        for (int u = 0; u < 4; u++) {
            float2 f01 = __half22float2(*(__half2*)&rv[u].x);
            float2 f23 = __half22float2(*(__half2*)&rv[u].y);
            acc.x += f01.x; acc.y += f01.y; acc.z += f23.x; acc.w += f23.y;
        }
    }
    for (; i < t; i++) {
        uint2 rv = xt2[g_src[i] * 32 + lane];
        float2 f01 = __half22float2(*(__half2*)&rv.x);
        float2 f23 = __half22float2(*(__half2*)&rv.y);
        acc.x += f01.x; acc.y += f01.y; acc.z += f23.x; acc.w += f23.y;
    }
    float dv = g_dinv[warp];
    __half2 o01 = __floats2half2_rn(dv * acc.x, dv * acc.y);
    __half2 o23 = __floats2half2_rn(dv * acc.z, dv * acc.w);
    uint2 p;
    p.x = *(unsigned int*)&o01;
    p.y = *(unsigned int*)&o23;
    ((uint2*)g_agg)[warp * 32 + lane] = p;
}

// ---------------- GEMM with packed f32x2 FMA ---------------------------------
// Main: D[128x128] = agg @ W^T (+b+bias, ReLU).
// write_xt=1 -> epilogue writes next x_tilde (NaN-sentinel select).
// FUSEOUT    -> second in-block GEMM: out = relu(D) @ Wf^T + bf (h never hits gmem).
template <bool FUSEOUT>
__global__ void __launch_bounds__(256)
k_gemm(const float* __restrict__ W, const float* __restrict__ b,
       const float* __restrict__ bias,
       const float* __restrict__ Wf, const float* __restrict__ bf,
       float* __restrict__ out, int write_xt) {
    __shared__ float sA[128 * 33];       // [r][kk] chunk
    __shared__ float sW[32 * 130];       // [kk][j] chunk, 8B-aligned pairs
    __shared__ float sB[128];
    __shared__ float sBf[64];
    int tid = threadIdx.x;
    int row0 = blockIdx.x * 128;
    int tr = tid >> 4, tc = tid & 15;

    if (tid < 128) sB[tid] = b[tid] + bias[tid];
    if (FUSEOUT && tid < 64) sBf[tid] = bf[tid];

    u64 acc[8][4];
#pragma unroll
    for (int ii = 0; ii < 8; ii++)
#pragma unroll
        for (int jj = 0; jj < 4; jj++) acc[ii][jj] = 0ull;

    const float4* W4 = (const float4*)W;

    for (int kc = 0; kc < 4; kc++) {
        const uint2* A2 = (const uint2*)g_agg;
        for (int t = tid; t < 128 * 8; t += 256) {
            int r = t >> 3, q = t & 7;
            uint2 v = (row0 + r < NN) ? A2[(size_t)(row0 + r) * 32 + kc * 8 + q]
                                      : make_uint2(0u, 0u);
            float2 f01 = __half22float2(*(__half2*)&v.x);
            float2 f23 = __half22float2(*(__half2*)&v.y);
            float* dst = &sA[r * 33 + q * 4];
            dst[0] = f01.x; dst[1] = f01.y; dst[2] = f23.x; dst[3] = f23.y;
        }
        for (int t = tid; t < 128 * 8; t += 256) {
            int j = t >> 3, q = t & 7;
            float4 v = W4[(size_t)j * 32 + kc * 8 + q];
            int kk = q * 4;
            sW[(kk + 0) * 130 + j] = v.x;
            sW[(kk + 1) * 130 + j] = v.y;
            sW[(kk + 2) * 130 + j] = v.z;
            sW[(kk + 3) * 130 + j] = v.w;
        }
        __syncthreads();
#pragma unroll
        for (int kk = 0; kk < 32; kk++) {
            u64 a2[8], w2[4];
#pragma unroll
            for (int ii = 0; ii < 8; ii++)
                a2[ii] = pack2(sA[(tr + 16 * ii) * 33 + kk]);
#pragma unroll
            for (int jj = 0; jj < 4; jj++)
                w2[jj] = *(const u64*)&sW[kk * 130 + 2 * tc + 32 * jj];
#pragma unroll
            for (int ii = 0; ii < 8; ii++)
#pragma unroll
                for (int jj = 0; jj < 4; jj++)
                    fma2(acc[ii][jj], a2[ii], w2[jj]);
        }
        __syncthreads();
    }

    if (!FUSEOUT) {
        // layers 1-2: epilogue writes next x_tilde only
#pragma unroll
        for (int ii = 0; ii < 8; ii++) {
            int r = row0 + tr + 16 * ii;
            if (r >= NN) continue;
            float dv = g_dinv[r];
#pragma unroll
            for (int jj = 0; jj < 4; jj++) {
                int j0 = 2 * tc + 32 * jj;
                float2 v = unpack2(acc[ii][jj]);
                v.x = fmaxf(v.x + sB[j0], 0.f);
                v.y = fmaxf(v.y + sB[j0 + 1], 0.f);
                size_t idx = (size_t)r * DD + j0;
                __half2 x0 = *(const __half2*)&g_x0[idx];
                float2 x0f = __half22float2(x0);
                float t0 = isnan(x0f.x) ? dv * v.x : x0f.x;
                float t1 = isnan(x0f.y) ? dv * v.y : x0f.y;
                *(__half2*)&g_xt[idx] = __floats2half2_rn(t0, t1);
            }
        }
    } else {
        // layer 3 + final fc fused: h = relu(acc + sB) stays in smem chunks
        const float4* Wf4 = (const float4*)Wf;
        u64 acc2[8][2];
#pragma unroll
        for (int ii = 0; ii < 8; ii++) { acc2[ii][0] = 0ull; acc2[ii][1] = 0ull; }

        for (int kc2 = 0; kc2 < 4; kc2++) {
            // stage h chunk (cols 32*kc2..+31) into sA from registers
#pragma unroll
            for (int ii = 0; ii < 8; ii++) {
                int rloc = tr + 16 * ii;
                int j0 = 2 * tc + 32 * kc2;
                float2 v = unpack2(acc[ii][kc2]);
                sA[rloc * 33 + 2 * tc]     = fmaxf(v.x + sB[j0], 0.f);
                sA[rloc * 33 + 2 * tc + 1] = fmaxf(v.y + sB[j0 + 1], 0.f);
            }
            // Wf chunk: Wf[64][128], k-cols 32*kc2..+31 -> sW[kk][j]
            for (int t = tid; t < 64 * 8; t += 256) {
                int j = t >> 3, q = t & 7;
                float4 v = Wf4[(size_t)j * 32 + kc2 * 8 + q];
                int kk = q * 4;
                sW[(kk + 0) * 130 + j] = v.x;
                sW[(kk + 1) * 130 + j] = v.y;
                sW[(kk + 2) * 130 + j] = v.z;
                sW[(kk + 3) * 130 + j] = v.w;
            }
            __syncthreads();
#pragma unroll
            for (int kk = 0; kk < 32; kk++) {
                u64 a2[8], w2[2];
#pragma unroll
                for (int ii = 0; ii < 8; ii++)
                    a2[ii] = pack2(sA[(tr + 16 * ii) * 33 + kk]);
                w2[0] = *(const u64*)&sW[kk * 130 + 2 * tc];
                w2[1] = *(const u64*)&sW[kk * 130 + 2 * tc + 32];
#pragma unroll
                for (int ii = 0; ii < 8; ii++) {
                    fma2(acc2[ii][0], a2[ii], w2[0]);
                    fma2(acc2[ii][1], a2[ii], w2[1]);
                }
            }
            __syncthreads();
        }
#pragma unroll
        for (int ii = 0; ii < 8; ii++) {
            int r = row0 + tr + 16 * ii;
            if (r >= NN) continue;
#pragma unroll
            for (int jj = 0; jj < 2; jj++) {
                int j0 = 2 * tc + 32 * jj;
                float2 v = unpack2(acc2[ii][jj]);
                v.x += sBf[j0];
                v.y += sBf[j0 + 1];
                *(float2*)&out[(size_t)r * OUTC + j0] = v;
            }
        }
    }
}

// ---------------- launch ----------------------------------------------------
extern "C" void kernel_launch(void* const* d_in, const int* in_sizes, int n_in,
                              void* d_out, int out_size) {
    const int* ei = (const int*)d_in[0];   // [2,E], int32 or int64 (detected)
    const float* x = (const float*)d_in[2];
    const void*  M = d_in[3];              // bool or int32 (detected)
    const float* W1 = (const float*)d_in[4];
    const float* b1 = (const float*)d_in[5];
    const float* c1 = (const float*)d_in[6];
    const float* W2 = (const float*)d_in[7];
    const float* b2 = (const float*)d_in[8];
    const float* c2 = (const float*)d_in[9];
    const float* W3 = (const float*)d_in[10];
    const float* b3 = (const float*)d_in[11];
    const float* c3 = (const float*)d_in[12];
    const float* Wf = (const float*)d_in[13];
    const float* bf = (const float*)d_in[14];
    float* out = (float*)d_out;

    const int TB = 256;
    int nb_n = (NN + TB - 1) / TB;
    int nb_e = (EE + TB - 1) / TB;
    int nb_xt = (NN * DD / 4 + TB - 1) / TB;
    int nb_spmm = (NN * 32 + TB - 1) / TB;   // 1 warp per node
    int nb_gemm = (NN + 127) / 128;

    k_init<<<nb_n, TB>>>(ei, (const unsigned int*)M);
    k_count<<<nb_e, TB>>>(ei);
    k_scanA<<<NBLK, 1024>>>();
    k_fix_xt<<<nb_xt, TB>>>(x, M);
    k_bucket<<<nb_e, TB>>>(ei);

    k_spmm<<<nb_spmm, TB>>>();
    k_gemm<false><<<nb_gemm, TB>>>(W1, b1, c1, nullptr, nullptr, nullptr, 1);
    k_spmm<<<nb_spmm, TB>>>();
    k_gemm<false><<<nb_gemm, TB>>>(W2, b2, c2, nullptr, nullptr, nullptr, 1);
    k_spmm<<<nb_spmm, TB>>>();
    k_gemm<true><<<nb_gemm, TB>>>(W3, b3, c3, Wf, bf, out, 0);
}

// round 15
// speedup vs baseline: 1.0257x; 1.0257x over previous
#include <cuda_runtime.h>
#include <cuda_fp16.h>
#include <math.h>
#include <stdint.h>

#define NN 50000
#define EE 800000
#define DD 128
#define OUTC 64
#define NBLK ((NN + 1023) / 1024)   // 49 scan blocks

typedef unsigned long long u64;

// ---------------- scratch (device globals; no allocation allowed) ----------
__device__ int   g_ei_is64;
__device__ int   g_m_is32;
__device__ int   g_deg[NN];
__device__ float g_dinv[NN];
__device__ int   g_off[NN + 1];
__device__ int   g_bsum[64];        // raw per-block sums from scanA
__device__ int   g_rank[EE];        // per-edge rank within its column
__device__ int   g_src[EE];
__device__ __half g_xt[NN * DD];    // x_tilde, fp16, pre-scaled by dinv[row]
__device__ __half g_x0[NN * DD];    // hrn(dinv*x) where mask=1, NaN where mask=0
__device__ __half g_agg[NN * DD];   // aggregated messages (fp16)
__device__ __half g_h[NN * DD];     // layer-3 activations (fp16)

// ---------------- f32x2 packed math ----------------------------------------
__device__ __forceinline__ u64 pack2(float s) {
    u64 d;
    asm("mov.b64 %0, {%1, %1};" : "=l"(d) : "f"(s));
    return d;
}
__device__ __forceinline__ void fma2(u64& acc, u64 a, u64 b) {
    asm("fma.rn.f32x2 %0, %1, %2, %0;" : "+l"(acc) : "l"(a), "l"(b));
}
__device__ __forceinline__ float2 unpack2(u64 v) {
    float lo, hi;
    asm("mov.b64 {%0, %1}, %2;" : "=f"(lo), "=f"(hi) : "l"(v));
    return make_float2(lo, hi);
}

// ---------------- init: zero deg + dtype detection ---------------------------
__global__ void k_init(const int* __restrict__ ei, const unsigned int* __restrict__ Mw) {
    int i = blockIdx.x * blockDim.x + threadIdx.x;
    if (i < NN) g_deg[i] = 0;
    if (blockIdx.x == 0) {
        __shared__ int s_or, s_gt;
        if (threadIdx.x == 0) { s_or = 0; s_gt = 0; }
        __syncthreads();
        int t = threadIdx.x;
        if (ei[2 * t + 1] != 0) atomicOr(&s_or, 1);
        if (Mw[t] > 1u)         atomicOr(&s_gt, 1);
        __syncthreads();
        if (threadIdx.x == 0) { g_ei_is64 = (s_or == 0); g_m_is32 = (s_gt == 0); }
    }
}

// ---------------- CSC build: count assigns per-edge ranks --------------------
__global__ void k_count(const int* __restrict__ ei) {
    int e = blockIdx.x * blockDim.x + threadIdx.x;
    if (e >= EE) return;
    int c = g_ei_is64 ? ei[2 * (EE + e)] : ei[EE + e];
    g_rank[e] = atomicAdd(&g_deg[c], 1);
}

__global__ void k_scanA() {
    __shared__ int wsum[32];
    int tid = threadIdx.x, lane = tid & 31, wid = tid >> 5;
    int i = blockIdx.x * 1024 + tid;
    int v = (i < NN) ? g_deg[i] : 0;
    if (i < NN) g_dinv[i] = (v > 0) ? rsqrtf((float)v) : 0.0f;
    int x = v;
#pragma unroll
    for (int o = 1; o < 32; o <<= 1) {
        int t = __shfl_up_sync(0xffffffffu, x, o);
        if (lane >= o) x += t;
    }
    if (lane == 31) wsum[wid] = x;
    __syncthreads();
    if (wid == 0) {
        int s = wsum[lane];
#pragma unroll
        for (int o = 1; o < 32; o <<= 1) {
            int t = __shfl_up_sync(0xffffffffu, s, o);
            if (lane >= o) s += t;
        }
        wsum[lane] = s;
    }
    __syncthreads();
    int woff = (wid > 0) ? wsum[wid - 1] : 0;
    if (i < NN) g_off[i + 1] = woff + x;          // block-local inclusive
    if (tid == 1023) g_bsum[blockIdx.x] = woff + x;   // raw block sum
}

// ---------------- fix offsets (local bsum prefix) + x_tilde/x0 init ----------
__global__ void k_fix_xt(const float* __restrict__ x, const void* __restrict__ M) {
    __shared__ int sb[NBLK];
    int tid = threadIdx.x;
    int gid = blockIdx.x * blockDim.x + tid;
    if (tid < NBLK) sb[tid] = g_bsum[tid];
    __syncthreads();
    if (tid == 0) {                 // exclusive prefix of 49 values
        int acc = 0;
#pragma unroll
        for (int q = 0; q < NBLK; q++) { int t = sb[q]; sb[q] = acc; acc += t; }
    }
    __syncthreads();
    if (gid < NN) g_off[gid + 1] += sb[gid >> 10];
    if (gid == 0) g_off[0] = 0;

    int i = gid;                                   // over (N*D)/4
    if (i >= NN * DD / 4) return;
    uchar4 mv;
    if (g_m_is32) {
        int4 w = ((const int4*)M)[i];
        mv = make_uchar4((unsigned char)w.x, (unsigned char)w.y,
                         (unsigned char)w.z, (unsigned char)w.w);
    } else {
        mv = ((const uchar4*)M)[i];
    }
    float dv = g_dinv[i >> 5];
    float4 xv = ((const float4*)x)[i];
    float s0 = dv * xv.x, s1 = dv * xv.y, s2 = dv * xv.z, s3 = dv * xv.w;
    __half2 xt01 = __floats2half2_rn(mv.x ? s0 : 0.0f, mv.y ? s1 : 0.0f);
    __half2 xt23 = __floats2half2_rn(mv.z ? s2 : 0.0f, mv.w ? s3 : 0.0f);
    const float QNAN = __int_as_float(0x7fc00000);
    __half2 x001 = __floats2half2_rn(mv.x ? s0 : QNAN, mv.y ? s1 : QNAN);
    __half2 x023 = __floats2half2_rn(mv.z ? s2 : QNAN, mv.w ? s3 : QNAN);
    uint2 pxt, px0;
    pxt.x = *(unsigned int*)&xt01; pxt.y = *(unsigned int*)&xt23;
    px0.x = *(unsigned int*)&x001; px0.y = *(unsigned int*)&x023;
    ((uint2*)g_xt)[i] = pxt;
    ((uint2*)g_x0)[i] = px0;
}

// ---------------- bucket: pure scattered store (no atomics) ------------------
__global__ void k_bucket(const int* __restrict__ ei) {
    int e = blockIdx.x * blockDim.x + threadIdx.x;
    if (e >= EE) return;
    int r, c;
    if (g_ei_is64) { r = ei[2 * e]; c = ei[2 * (EE + e)]; }
    else           { r = ei[e];     c = ei[EE + e]; }
    g_src[g_off[c] + g_rank[e]] = r;
}

// ---------------- SpMM: one warp per destination node (fp16 in/out) ----------
__global__ void k_spmm() {
    int warp = (blockIdx.x * blockDim.x + threadIdx.x) >> 5;
    if (warp >= NN) return;
    int lane = threadIdx.x & 31;
    int s = g_off[warp], t = g_off[warp + 1];
    const uint2* xt2 = (const uint2*)g_xt;   // 8B = 4 halfs per lane
    float4 acc = make_float4(0.f, 0.f, 0.f, 0.f);
    int i = s;
    for (; i + 8 <= t; i += 8) {
        uint2 rv[8];
#pragma unroll
        for (int u = 0; u < 8; u++) rv[u] = xt2[g_src[i + u] * 32 + lane];
#pragma unroll
        for (int u = 0; u < 8; u++) {
            float2 f01 = __half22float2(*(__half2*)&rv[u].x);
            float2 f23 = __half22float2(*(__half2*)&rv[u].y);
            acc.x += f01.x; acc.y += f01.y; acc.z += f23.x; acc.w += f23.y;
        }
    }
    for (; i + 4 <= t; i += 4) {
        uint2 rv[4];
#pragma unroll
        for (int u = 0; u < 4; u++) rv[u] = xt2[g_src[i + u] * 32 + lane];
#pragma unroll
        for (int u = 0; u < 4; u++) {
            float2 f01 = __half22float2(*(__half2*)&rv[u].x);
            float2 f23 = __half22float2(*(__half2*)&rv[u].y);
            acc.x += f01.x; acc.y += f01.y; acc.z += f23.x; acc.w += f23.y;
        }
    }
    for (; i < t; i++) {
        uint2 rv = xt2[g_src[i] * 32 + lane];
        float2 f01 = __half22float2(*(__half2*)&rv.x);
        float2 f23 = __half22float2(*(__half2*)&rv.y);
        acc.x += f01.x; acc.y += f01.y; acc.z += f23.x; acc.w += f23.y;
    }
    float dv = g_dinv[warp];
    __half2 o01 = __floats2half2_rn(dv * acc.x, dv * acc.y);
    __half2 o23 = __floats2half2_rn(dv * acc.z, dv * acc.w);
    uint2 p;
    p.x = *(unsigned int*)&o01;
    p.y = *(unsigned int*)&o23;
    ((uint2*)g_agg)[warp * 32 + lane] = p;
}

// ---------------- GEMM with packed f32x2 FMA ---------------------------------
// D[128 x NOUT] = A[128 x 128] @ W[NOUT x 128]^T.
// A is fp16: g_agg (hidden) or g_h (final). Hidden epilogue: NaN-sentinel xt,
// or fp16 h (layer 3). Final epilogue: out = D + bf.
template <int NOUT, bool FINAL>
__global__ void __launch_bounds__(256)
k_gemm(const float* __restrict__ W, const float* __restrict__ b,
       const float* __restrict__ bias,
       float* __restrict__ out, int write_xt) {
    constexpr int NPAIR = NOUT / 32;
    __shared__ float sA[128 * 33];       // [r][kk] chunk
    __shared__ float sW[32 * 130];       // [kk][j] chunk, 8B-aligned pairs
    __shared__ float sB[128];
    int tid = threadIdx.x;
    int row0 = blockIdx.x * 128;
    int tr = tid >> 4, tc = tid & 15;

    if (tid < NOUT) sB[tid] = FINAL ? b[tid] : (b[tid] + bias[tid]);

    u64 acc[8][NPAIR];
#pragma unroll
    for (int ii = 0; ii < 8; ii++)
#pragma unroll
        for (int jj = 0; jj < NPAIR; jj++) acc[ii][jj] = 0ull;

    const float4* W4 = (const float4*)W;
    const uint2* A2 = (const uint2*)(FINAL ? g_h : g_agg);

    for (int kc = 0; kc < 4; kc++) {
        for (int t = tid; t < 128 * 8; t += 256) {
            int r = t >> 3, q = t & 7;
            uint2 v = (row0 + r < NN) ? A2[(size_t)(row0 + r) * 32 + kc * 8 + q]
                                      : make_uint2(0u, 0u);
            float2 f01 = __half22float2(*(__half2*)&v.x);
            float2 f23 = __half22float2(*(__half2*)&v.y);
            float* dst = &sA[r * 33 + q * 4];
            dst[0] = f01.x; dst[1] = f01.y; dst[2] = f23.x; dst[3] = f23.y;
        }
        for (int t = tid; t < NOUT * 8; t += 256) {
            int j = t >> 3, q = t & 7;
            float4 v = W4[(size_t)j * 32 + kc * 8 + q];
            int kk = q * 4;
            sW[(kk + 0) * 130 + j] = v.x;
            sW[(kk + 1) * 130 + j] = v.y;
            sW[(kk + 2) * 130 + j] = v.z;
            sW[(kk + 3) * 130 + j] = v.w;
        }
        __syncthreads();
#pragma unroll
        for (int kk = 0; kk < 32; kk++) {
            u64 a2[8], w2[NPAIR];
#pragma unroll
            for (int ii = 0; ii < 8; ii++)
                a2[ii] = pack2(sA[(tr + 16 * ii) * 33 + kk]);
#pragma unroll
            for (int jj = 0; jj < NPAIR; jj++)
                w2[jj] = *(const u64*)&sW[kk * 130 + 2 * tc + 32 * jj];
#pragma unroll
            for (int ii = 0; ii < 8; ii++)
#pragma unroll
                for (int jj = 0; jj < NPAIR; jj++)
                    fma2(acc[ii][jj], a2[ii], w2[jj]);
        }
        __syncthreads();
    }

#pragma unroll
    for (int ii = 0; ii < 8; ii++) {
        int r = row0 + tr + 16 * ii;
        if (r >= NN) continue;
        float dv = (!FINAL) ? g_dinv[r] : 0.f;
#pragma unroll
        for (int jj = 0; jj < NPAIR; jj++) {
            int j0 = 2 * tc + 32 * jj;
            float2 v = unpack2(acc[ii][jj]);
            if (FINAL) {
                v.x += sB[j0];
                v.y += sB[j0 + 1];
                *(float2*)&out[(size_t)r * OUTC + j0] = v;
            } else {
                v.x = fmaxf(v.x + sB[j0], 0.f);
                v.y = fmaxf(v.y + sB[j0 + 1], 0.f);
                size_t idx = (size_t)r * DD + j0;
                if (write_xt) {
                    // xt_next = isnan(x0) ? dinv*h : x0   (x0 already = hrn(dinv*x))
                    __half2 x0 = *(const __half2*)&g_x0[idx];
                    float2 x0f = __half22float2(x0);
                    float t0 = isnan(x0f.x) ? dv * v.x : x0f.x;
                    float t1 = isnan(x0f.y) ? dv * v.y : x0f.y;
                    *(__half2*)&g_xt[idx] = __floats2half2_rn(t0, t1);
                } else {
                    // layer 3: h stored fp16 for the final GEMM
                    *(__half2*)&g_h[idx] = __floats2half2_rn(v.x, v.y);
                }
            }
        }
    }
}

// ---------------- launch ----------------------------------------------------
extern "C" void kernel_launch(void* const* d_in, const int* in_sizes, int n_in,
                              void* d_out, int out_size) {
    const int* ei = (const int*)d_in[0];   // [2,E], int32 or int64 (detected)
    const float* x = (const float*)d_in[2];
    const void*  M = d_in[3];              // bool or int32 (detected)
    const float* W1 = (const float*)d_in[4];
    const float* b1 = (const float*)d_in[5];
    const float* c1 = (const float*)d_in[6];
    const float* W2 = (const float*)d_in[7];
    const float* b2 = (const float*)d_in[8];
    const float* c2 = (const float*)d_in[9];
    const float* W3 = (const float*)d_in[10];
    const float* b3 = (const float*)d_in[11];
    const float* c3 = (const float*)d_in[12];
    const float* Wf = (const float*)d_in[13];
    const float* bf = (const float*)d_in[14];
    float* out = (float*)d_out;

    const int TB = 256;
    int nb_n = (NN + TB - 1) / TB;
    int nb_e = (EE + TB - 1) / TB;
    int nb_xt = (NN * DD / 4 + TB - 1) / TB;
    int nb_spmm = (NN * 32 + TB - 1) / TB;   // 1 warp per node
    int nb_gemm = (NN + 127) / 128;

    k_init<<<nb_n, TB>>>(ei, (const unsigned int*)M);
    k_count<<<nb_e, TB>>>(ei);
    k_scanA<<<NBLK, 1024>>>();
    k_fix_xt<<<nb_xt, TB>>>(x, M);
    k_bucket<<<nb_e, TB>>>(ei);

    k_spmm<<<nb_spmm, TB>>>();
    k_gemm<128, false><<<nb_gemm, TB>>>(W1, b1, c1, nullptr, 1);
    k_spmm<<<nb_spmm, TB>>>();
    k_gemm<128, false><<<nb_gemm, TB>>>(W2, b2, c2, nullptr, 1);
    k_spmm<<<nb_spmm, TB>>>();
    k_gemm<128, false><<<nb_gemm, TB>>>(W3, b3, c3, nullptr, 0);
    k_gemm<64, true><<<nb_gemm, TB>>>(Wf, bf, nullptr, out, 0);
}

// round 16
// speedup vs baseline: 1.0981x; 1.0706x over previous
#include <cuda_runtime.h>
#include <cuda_fp16.h>
#include <math.h>
#include <stdint.h>

#define NN 50000
#define EE 800000
#define DD 128
#define OUTC 64
#define NBLK ((NN + 1023) / 1024)   // 49 scan blocks

typedef unsigned long long u64;

// ---------------- scratch (device globals; no allocation allowed) ----------
__device__ int   g_ei_is64;
__device__ int   g_m_is32;
__device__ int   g_deg[NN];          // zero-init at load; re-zeroed by k_bucket
__device__ float g_dinv[NN];
__device__ int   g_off[NN + 1];
__device__ int   g_bsum[64];         // raw per-block sums from scanA
__device__ int   g_rank[EE];         // per-edge rank within its column
__device__ int   g_src[EE];
__device__ __half g_xt[NN * DD];     // x_tilde, fp16, pre-scaled by dinv[row]
__device__ __half g_x0[NN * DD];     // hrn(dinv*x) where mask=1, NaN where mask=0
__device__ __half g_agg[NN * DD];    // aggregated messages (fp16)
__device__ __half g_h[NN * DD];      // layer-3 activations (fp16)

// ---------------- f32x2 packed math ----------------------------------------
__device__ __forceinline__ u64 pack2(float s) {
    u64 d;
    asm("mov.b64 %0, {%1, %1};" : "=l"(d) : "f"(s));
    return d;
}
__device__ __forceinline__ void fma2(u64& acc, u64 a, u64 b) {
    asm("fma.rn.f32x2 %0, %1, %2, %0;" : "+l"(acc) : "l"(a), "l"(b));
}
__device__ __forceinline__ float2 unpack2(u64 v) {
    float lo, hi;
    asm("mov.b64 {%0, %1}, %2;" : "=f"(lo), "=f"(hi) : "l"(v));
    return make_float2(lo, hi);
}

// ---------------- count + dtype detection (init folded in) ------------------
// g_deg arrives zeroed (static init on first call; k_bucket re-zeroes it for
// the next replay). Each block self-detects ei dtype from 256 L2-hot words;
// block 0 publishes both flags for the later kernels.
__global__ void k_count(const int* __restrict__ ei, const unsigned int* __restrict__ Mw) {
    __shared__ int s_or;
    if (threadIdx.x == 0) s_or = 0;
    __syncthreads();
    if (threadIdx.x < 256 && ei[2 * threadIdx.x + 1] != 0) atomicOr(&s_or, 1);
    __syncthreads();
    int is64 = (s_or == 0);
    if (blockIdx.x == 0) {
        __shared__ int s_gt;
        if (threadIdx.x == 0) s_gt = 0;
        __syncthreads();
        if (threadIdx.x < 256 && Mw[threadIdx.x] > 1u) atomicOr(&s_gt, 1);
        __syncthreads();
        if (threadIdx.x == 0) { g_ei_is64 = is64; g_m_is32 = (s_gt == 0); }
    }
    int e = blockIdx.x * blockDim.x + threadIdx.x;
    if (e >= EE) return;
    int c = is64 ? ei[2 * (EE + e)] : ei[EE + e];
    g_rank[e] = atomicAdd(&g_deg[c], 1);
}

__global__ void k_scanA() {
    __shared__ int wsum[32];
    int tid = threadIdx.x, lane = tid & 31, wid = tid >> 5;
    int i = blockIdx.x * 1024 + tid;
    int v = (i < NN) ? g_deg[i] : 0;
    if (i < NN) g_dinv[i] = (v > 0) ? rsqrtf((float)v) : 0.0f;
    int x = v;
#pragma unroll
    for (int o = 1; o < 32; o <<= 1) {
        int t = __shfl_up_sync(0xffffffffu, x, o);
        if (lane >= o) x += t;
    }
    if (lane == 31) wsum[wid] = x;
    __syncthreads();
    if (wid == 0) {
        int s = wsum[lane];
#pragma unroll
        for (int o = 1; o < 32; o <<= 1) {
            int t = __shfl_up_sync(0xffffffffu, s, o);
            if (lane >= o) s += t;
        }
        wsum[lane] = s;
    }
    __syncthreads();
    int woff = (wid > 0) ? wsum[wid - 1] : 0;
    if (i < NN) g_off[i + 1] = woff + x;          // block-local inclusive
    if (tid == 1023) g_bsum[blockIdx.x] = woff + x;   // raw block sum
}

// ---------------- fix offsets (local bsum prefix) + x_tilde/x0 init ----------
__global__ void k_fix_xt(const float* __restrict__ x, const void* __restrict__ M) {
    __shared__ int sb[NBLK];
    int tid = threadIdx.x;
    int gid = blockIdx.x * blockDim.x + tid;
    if (tid < NBLK) sb[tid] = g_bsum[tid];
    __syncthreads();
    if (tid == 0) {                 // exclusive prefix of 49 values
        int acc = 0;
#pragma unroll
        for (int q = 0; q < NBLK; q++) { int t = sb[q]; sb[q] = acc; acc += t; }
    }
    __syncthreads();
    if (gid < NN) g_off[gid + 1] += sb[gid >> 10];
    if (gid == 0) g_off[0] = 0;

    int i = gid;                                   // over (N*D)/4
    if (i >= NN * DD / 4) return;
    uchar4 mv;
    if (g_m_is32) {
        int4 w = ((const int4*)M)[i];
        mv = make_uchar4((unsigned char)w.x, (unsigned char)w.y,
                         (unsigned char)w.z, (unsigned char)w.w);
    } else {
        mv = ((const uchar4*)M)[i];
    }
    float dv = g_dinv[i >> 5];
    float4 xv = ((const float4*)x)[i];
    float s0 = dv * xv.x, s1 = dv * xv.y, s2 = dv * xv.z, s3 = dv * xv.w;
    __half2 xt01 = __floats2half2_rn(mv.x ? s0 : 0.0f, mv.y ? s1 : 0.0f);
    __half2 xt23 = __floats2half2_rn(mv.z ? s2 : 0.0f, mv.w ? s3 : 0.0f);
    const float QNAN = __int_as_float(0x7fc00000);
    __half2 x001 = __floats2half2_rn(mv.x ? s0 : QNAN, mv.y ? s1 : QNAN);
    __half2 x023 = __floats2half2_rn(mv.z ? s2 : QNAN, mv.w ? s3 : QNAN);
    uint2 pxt, px0;
    pxt.x = *(unsigned int*)&xt01; pxt.y = *(unsigned int*)&xt23;
    px0.x = *(unsigned int*)&x001; px0.y = *(unsigned int*)&x023;
    ((uint2*)g_xt)[i] = pxt;
    ((uint2*)g_x0)[i] = px0;
}

// ---------------- bucket: scattered store + deg re-zero for next replay ------
__global__ void k_bucket(const int* __restrict__ ei) {
    int e = blockIdx.x * blockDim.x + threadIdx.x;
    if (e >= EE) return;
    if (e < NN) g_deg[e] = 0;       // deg is dead after scanA; prep next replay
    int r, c;
    if (g_ei_is64) { r = ei[2 * e]; c = ei[2 * (EE + e)]; }
    else           { r = ei[e];     c = ei[EE + e]; }
    g_src[g_off[c] + g_rank[e]] = r;
}

// ---------------- SpMM: one warp per destination node (fp16 in/out) ----------
__global__ void k_spmm() {
    int warp = (blockIdx.x * blockDim.x + threadIdx.x) >> 5;
    if (warp >= NN) return;
    int lane = threadIdx.x & 31;
    int s = g_off[warp], t = g_off[warp + 1];
    const uint2* xt2 = (const uint2*)g_xt;   // 8B = 4 halfs per lane
    float4 acc = make_float4(0.f, 0.f, 0.f, 0.f);
    int i = s;
    for (; i + 8 <= t; i += 8) {
        uint2 rv[8];
#pragma unroll
        for (int u = 0; u < 8; u++) rv[u] = xt2[g_src[i + u] * 32 + lane];
#pragma unroll
        for (int u = 0; u < 8; u++) {
            float2 f01 = __half22float2(*(__half2*)&rv[u].x);
            float2 f23 = __half22float2(*(__half2*)&rv[u].y);
            acc.x += f01.x; acc.y += f01.y; acc.z += f23.x; acc.w += f23.y;
        }
    }
    for (; i + 4 <= t; i += 4) {
        uint2 rv[4];
#pragma unroll
        for (int u = 0; u < 4; u++) rv[u] = xt2[g_src[i + u] * 32 + lane];
#pragma unroll
        for (int u = 0; u < 4; u++) {
            float2 f01 = __half22float2(*(__half2*)&rv[u].x);
            float2 f23 = __half22float2(*(__half2*)&rv[u].y);
            acc.x += f01.x; acc.y += f01.y; acc.z += f23.x; acc.w += f23.y;
        }
    }
    for (; i < t; i++) {
        uint2 rv = xt2[g_src[i] * 32 + lane];
        float2 f01 = __half22float2(*(__half2*)&rv.x);
        float2 f23 = __half22float2(*(__half2*)&rv.y);
        acc.x += f01.x; acc.y += f01.y; acc.z += f23.x; acc.w += f23.y;
    }
    float dv = g_dinv[warp];
    __half2 o01 = __floats2half2_rn(dv * acc.x, dv * acc.y);
    __half2 o23 = __floats2half2_rn(dv * acc.z, dv * acc.w);
    uint2 p;
    p.x = *(unsigned int*)&o01;
    p.y = *(unsigned int*)&o23;
    ((uint2*)g_agg)[warp * 32 + lane] = p;
}

// ---------------- GEMM, 64-row tiles, 128 threads (anti-wave-quantization) ---
// D[64 x NOUT] = A[64 x 128] @ W[NOUT x 128]^T. A fp16 (g_agg / g_h).
template <int NOUT, bool FINAL>
__global__ void __launch_bounds__(128)
k_gemm(const float* __restrict__ W, const float* __restrict__ b,
       const float* __restrict__ bias,
       float* __restrict__ out, int write_xt) {
    constexpr int NPAIR = NOUT / 32;
    __shared__ float sA[64 * 33];        // [r][kk] chunk
    __shared__ float sW[32 * 130];       // [kk][j] chunk, 8B-aligned pairs
    __shared__ float sB[128];
    int tid = threadIdx.x;
    int row0 = blockIdx.x * 64;
    int tr = tid >> 4, tc = tid & 15;    // tr: 0..7

    if (tid < NOUT) sB[tid] = FINAL ? b[tid] : (b[tid] + bias[tid]);

    u64 acc[8][NPAIR];
#pragma unroll
    for (int ii = 0; ii < 8; ii++)
#pragma unroll
        for (int jj = 0; jj < NPAIR; jj++) acc[ii][jj] = 0ull;

    const float4* W4 = (const float4*)W;
    const uint2* A2 = (const uint2*)(FINAL ? g_h : g_agg);

    for (int kc = 0; kc < 4; kc++) {
        for (int t = tid; t < 64 * 8; t += 128) {
            int r = t >> 3, q = t & 7;
            uint2 v = (row0 + r < NN) ? A2[(size_t)(row0 + r) * 32 + kc * 8 + q]
                                      : make_uint2(0u, 0u);
            float2 f01 = __half22float2(*(__half2*)&v.x);
            float2 f23 = __half22float2(*(__half2*)&v.y);
            float* dst = &sA[r * 33 + q * 4];
            dst[0] = f01.x; dst[1] = f01.y; dst[2] = f23.x; dst[3] = f23.y;
        }
        for (int t = tid; t < NOUT * 8; t += 128) {
            int j = t >> 3, q = t & 7;
            float4 v = W4[(size_t)j * 32 + kc * 8 + q];
            int kk = q * 4;
            sW[(kk + 0) * 130 + j] = v.x;
            sW[(kk + 1) * 130 + j] = v.y;
            sW[(kk + 2) * 130 + j] = v.z;
            sW[(kk + 3) * 130 + j] = v.w;
        }
        __syncthreads();
#pragma unroll
        for (int kk = 0; kk < 32; kk++) {
            u64 a2[8], w2[NPAIR];
#pragma unroll
            for (int ii = 0; ii < 8; ii++)
                a2[ii] = pack2(sA[(tr + 8 * ii) * 33 + kk]);
#pragma unroll
            for (int jj = 0; jj < NPAIR; jj++)
                w2[jj] = *(const u64*)&sW[kk * 130 + 2 * tc + 32 * jj];
#pragma unroll
            for (int ii = 0; ii < 8; ii++)
#pragma unroll
                for (int jj = 0; jj < NPAIR; jj++)
                    fma2(acc[ii][jj], a2[ii], w2[jj]);
        }
        __syncthreads();
    }

#pragma unroll
    for (int ii = 0; ii < 8; ii++) {
        int r = row0 + tr + 8 * ii;
        if (r >= NN) continue;
        float dv = (!FINAL) ? g_dinv[r] : 0.f;
#pragma unroll
        for (int jj = 0; jj < NPAIR; jj++) {
            int j0 = 2 * tc + 32 * jj;
            float2 v = unpack2(acc[ii][jj]);
            if (FINAL) {
                v.x += sB[j0];
                v.y += sB[j0 + 1];
                *(float2*)&out[(size_t)r * OUTC + j0] = v;
            } else {
                v.x = fmaxf(v.x + sB[j0], 0.f);
                v.y = fmaxf(v.y + sB[j0 + 1], 0.f);
                size_t idx = (size_t)r * DD + j0;
                if (write_xt) {
                    // xt_next = isnan(x0) ? dinv*h : x0   (x0 already = hrn(dinv*x))
                    __half2 x0 = *(const __half2*)&g_x0[idx];
                    float2 x0f = __half22float2(x0);
                    float t0 = isnan(x0f.x) ? dv * v.x : x0f.x;
                    float t1 = isnan(x0f.y) ? dv * v.y : x0f.y;
                    *(__half2*)&g_xt[idx] = __floats2half2_rn(t0, t1);
                } else {
                    // layer 3: h stored fp16 for the final GEMM
                    *(__half2*)&g_h[idx] = __floats2half2_rn(v.x, v.y);
                }
            }
        }
    }
}

// ---------------- launch ----------------------------------------------------
extern "C" void kernel_launch(void* const* d_in, const int* in_sizes, int n_in,
                              void* d_out, int out_size) {
    const int* ei = (const int*)d_in[0];   // [2,E], int32 or int64 (detected)
    const float* x = (const float*)d_in[2];
    const void*  M = d_in[3];              // bool or int32 (detected)
    const float* W1 = (const float*)d_in[4];
    const float* b1 = (const float*)d_in[5];
    const float* c1 = (const float*)d_in[6];
    const float* W2 = (const float*)d_in[7];
    const float* b2 = (const float*)d_in[8];
    const float* c2 = (const float*)d_in[9];
    const float* W3 = (const float*)d_in[10];
    const float* b3 = (const float*)d_in[11];
    const float* c3 = (const float*)d_in[12];
    const float* Wf = (const float*)d_in[13];
    const float* bf = (const float*)d_in[14];
    float* out = (float*)d_out;

    const int TB = 256;
    int nb_e = (EE + TB - 1) / TB;
    int nb_xt = (NN * DD / 4 + TB - 1) / TB;
    int nb_spmm = (NN * 32 + TB - 1) / TB;   // 1 warp per node
    int nb_gemm = (NN + 63) / 64;            // 64-row tiles

    k_count<<<nb_e, TB>>>(ei, (const unsigned int*)M);
    k_scanA<<<NBLK, 1024>>>();
    k_fix_xt<<<nb_xt, TB>>>(x, M);
    k_bucket<<<nb_e, TB>>>(ei);

    k_spmm<<<nb_spmm, TB>>>();
    k_gemm<128, false><<<nb_gemm, 128>>>(W1, b1, c1, nullptr, 1);
    k_spmm<<<nb_spmm, TB>>>();
    k_gemm<128, false><<<nb_gemm, 128>>>(W2, b2, c2, nullptr, 1);
    k_spmm<<<nb_spmm, TB>>>();
    k_gemm<128, false><<<nb_gemm, 128>>>(W3, b3, c3, nullptr, 0);
    k_gemm<64, true><<<nb_gemm, 128>>>(Wf, bf, nullptr, out, 0);
}